// round 1
// baseline (speedup 1.0000x reference)
#include <cuda_runtime.h>
#include <cuda_bf16.h>
#include <math.h>

// Problem constants
#define NROWS 2048
#define NDIM  4096
#define ROWSTRIDE 8192   // features[:,0,:] -> stride 2*4096 floats
#define NCLS  8

// Phase-2 tiling
#define RT_ROWS 128
#define NRT     16        // 2048 / 128
#define CT_COLS 512       // 256 threads * 2 cols
#define NCT     8         // 4096 / 512

// ---------------- device scratch (static, no allocation) ----------------
__device__ float  g_off[NROWS];          // m + logZ per row
__device__ float  g_d[NROWS];            // d_i = sum_k p*logp per row
__device__ int    g_perm[NROWS];         // rows sorted by label (stable)
__device__ int    g_slab[NROWS];         // label of g_perm[r]
__device__ int    g_nc[NCLS];            // class counts
__device__ float  g_P[NRT][NCLS][NDIM];  // per-rowtile per-class sum of p
__device__ float  g_L[NRT][NCLS][NDIM];  // per-rowtile per-class sum of logp
__device__ double g_dot[NRT][2];         // per-block (dot_same, dot_all) partials

// ---------------- fast exp on the FMA pipe (no MUFU) ----------------
__device__ __forceinline__ float fast_exp(float x) {
    float y = x * 1.4426950408889634f;     // x * log2(e)
    y = fmaxf(y, -126.0f);
    float t = y + 12582912.0f;             // round-to-nearest via magic constant
    int   ni = __float_as_int(t) - 0x4B400000;
    float n  = t - 12582912.0f;
    float r  = y - n;                      // r in [-0.5, 0.5]
    // 2^r, Taylor deg-6 in ln2 (max rel err ~1.2e-7 on [-0.5,0.5])
    const float c6 = 1.5403530393381609e-4f;
    const float c5 = 1.3333558146428443e-3f;
    const float c4 = 9.618129107628477e-3f;
    const float c3 = 5.550410866482158e-2f;
    const float c2 = 2.402265069591007e-1f;
    const float c1 = 6.931471805599453e-1f;
    float q = c6;
    q = fmaf(q, r, c5);
    q = fmaf(q, r, c4);
    q = fmaf(q, r, c3);
    q = fmaf(q, r, c2);
    q = fmaf(q, r, c1);
    q = fmaf(q, r, 1.0f);
    return q * __int_as_float((ni + 127) << 23);
}

// ---------------- reduction helpers ----------------
__device__ __forceinline__ float warpRedMax(float v) {
    #pragma unroll
    for (int s = 16; s > 0; s >>= 1) v = fmaxf(v, __shfl_xor_sync(0xffffffffu, v, s));
    return v;
}
__device__ __forceinline__ float warpRedSum(float v) {
    #pragma unroll
    for (int s = 16; s > 0; s >>= 1) v += __shfl_xor_sync(0xffffffffu, v, s);
    return v;
}
__device__ __forceinline__ double warpRedSumD(double v) {
    #pragma unroll
    for (int s = 16; s > 0; s >>= 1) v += __shfl_xor_sync(0xffffffffu, v, s);
    return v;
}

// ---------------- kernel 0: stable counting sort of rows by label ----------------
__global__ void k_perm(const int* __restrict__ labels) {
    __shared__ int slab[NROWS];
    __shared__ int snc[NCLS];
    __shared__ int scs[NCLS + 1];
    int tid = threadIdx.x;
    for (int i = tid; i < NROWS; i += 256) slab[i] = labels[i];
    __syncthreads();

    int w = tid >> 5, lane = tid & 31;
    if (w < NCLS) {
        int cnt = 0;
        for (int base = 0; base < NROWS; base += 32) {
            int l = slab[base + lane];
            unsigned b = __ballot_sync(0xffffffffu, l == w);
            cnt += __popc(b);
        }
        if (lane == 0) snc[w] = cnt;
    }
    __syncthreads();
    if (tid == 0) {
        int acc = 0;
        for (int c = 0; c < NCLS; c++) { scs[c] = acc; g_nc[c] = snc[c]; acc += snc[c]; }
        scs[NCLS] = acc;
    }
    __syncthreads();
    if (w < NCLS) {
        int off = scs[w];
        for (int base = 0; base < NROWS; base += 32) {
            int l = slab[base + lane];
            unsigned b = __ballot_sync(0xffffffffu, l == w);
            int pre = __popc(b & ((1u << lane) - 1u));
            if (l == w) { g_perm[off + pre] = base + lane; g_slab[off + pre] = w; }
            off += __popc(b);
        }
    }
}

// ---------------- kernel 1: per-row softmax stats + diag ----------------
// o_i = max + log(sum exp(x - max));  d_i = (sum e*x)/Z - o_i
__global__ void __launch_bounds__(256) k_rowstats(const float* __restrict__ feat) {
    int row = blockIdx.x;
    const float* x = feat + (size_t)row * ROWSTRIDE;
    int tid = threadIdx.x, wid = tid >> 5, lane = tid & 31;

    float v[16];
    float m = -INFINITY;
    #pragma unroll
    for (int u = 0; u < 16; u++) { v[u] = x[tid + 256 * u]; m = fmaxf(m, v[u]); }

    __shared__ float sred[8];
    __shared__ float sbm;
    float wm = warpRedMax(m);
    if (lane == 0) sred[wid] = wm;
    __syncthreads();
    if (tid == 0) {
        float mm = sred[0];
        #pragma unroll
        for (int i = 1; i < 8; i++) mm = fmaxf(mm, sred[i]);
        sbm = mm;
    }
    __syncthreads();
    m = sbm;

    float s = 0.f, s2 = 0.f;
    #pragma unroll
    for (int u = 0; u < 16; u++) {
        float e = fast_exp(v[u] - m);
        s += e;
        s2 = fmaf(e, v[u], s2);
    }
    __shared__ float2 sred2[8];
    float ws  = warpRedSum(s);
    float ws2 = warpRedSum(s2);
    if (lane == 0) sred2[wid] = make_float2(ws, ws2);
    __syncthreads();
    if (tid == 0) {
        float Z = 0.f, S2 = 0.f;
        #pragma unroll
        for (int i = 0; i < 8; i++) { Z += sred2[i].x; S2 += sred2[i].y; }
        float o = m + logf(Z);
        g_off[row] = o;
        g_d[row]   = S2 / Z - o;
    }
}

// ---------------- kernel 2: per-class column sums of p and logp ----------------
// grid (NCT, NRT), 256 threads, 2 columns per thread, rows visited in
// class-sorted order so only ONE running (P,L) accumulator pair is needed.
__global__ void __launch_bounds__(256) k_classsum(const float* __restrict__ feat) {
    __shared__ float s_off[RT_ROWS];
    __shared__ int   s_row[RT_ROWS];
    __shared__ int   s_cls[RT_ROWS];
    int tid = threadIdx.x;
    int rt = blockIdx.y, ct = blockIdx.x;
    int rbase = rt * RT_ROWS;
    int k = ct * CT_COLS + tid * 2;

    if (tid < RT_ROWS) {
        int pr = g_perm[rbase + tid];
        s_row[tid] = pr;
        s_off[tid] = g_off[pr];
        s_cls[tid] = g_slab[rbase + tid];
    }
    // zero this block's slice for all classes (flush only writes present classes)
    float2 z = make_float2(0.f, 0.f);
    #pragma unroll
    for (int c = 0; c < NCLS; c++) {
        *(float2*)&g_P[rt][c][k] = z;
        *(float2*)&g_L[rt][c][k] = z;
    }
    __syncthreads();

    float P0 = 0.f, P1 = 0.f, L0 = 0.f, L1 = 0.f;
    int cur = s_cls[0];
    #pragma unroll 4
    for (int r = 0; r < RT_ROWS; r++) {
        int cl = s_cls[r];
        if (cl != cur) {               // warp-uniform, rare
            g_P[rt][cur][k] = P0; g_P[rt][cur][k + 1] = P1;
            g_L[rt][cur][k] = L0; g_L[rt][cur][k + 1] = L1;
            P0 = P1 = L0 = L1 = 0.f;
            cur = cl;
        }
        const float2 xv = *(const float2*)(feat + (size_t)s_row[r] * ROWSTRIDE + k);
        float o = s_off[r];
        float t0 = xv.x - o, t1 = xv.y - o;   // logp
        P0 += fast_exp(t0);
        P1 += fast_exp(t1);
        L0 += t0;
        L1 += t1;
    }
    g_P[rt][cur][k] = P0; g_P[rt][cur][k + 1] = P1;
    g_L[rt][cur][k] = L0; g_L[rt][cur][k + 1] = L1;
}

// ---------------- kernel 3: reduce partials, compute dots ----------------
__global__ void __launch_bounds__(256) k_dots() {
    int tid = threadIdx.x, wid = tid >> 5, lane = tid & 31;
    int k = blockIdx.x * 256 + tid;

    float pc[NCLS], lc[NCLS];
    #pragma unroll
    for (int c = 0; c < NCLS; c++) { pc[c] = 0.f; lc[c] = 0.f; }
    for (int rt = 0; rt < NRT; rt++) {
        #pragma unroll
        for (int c = 0; c < NCLS; c++) {
            pc[c] += g_P[rt][c][k];
            lc[c] += g_L[rt][c][k];
        }
    }
    double dsame = 0.0;
    float Ps = 0.f, Ls = 0.f;
    #pragma unroll
    for (int c = 0; c < NCLS; c++) {
        dsame += (double)pc[c] * (double)lc[c];
        Ps += pc[c];
        Ls += lc[c];
    }
    double dall = (double)Ps * (double)Ls;

    __shared__ double sd[8][2];
    double w0 = warpRedSumD(dsame);
    double w1 = warpRedSumD(dall);
    if (lane == 0) { sd[wid][0] = w0; sd[wid][1] = w1; }
    __syncthreads();
    if (tid == 0) {
        double a = 0.0, b = 0.0;
        #pragma unroll
        for (int i = 0; i < 8; i++) { a += sd[i][0]; b += sd[i][1]; }
        g_dot[blockIdx.x][0] = a;
        g_dot[blockIdx.x][1] = b;
    }
}

// ---------------- kernel 4: final combine ----------------
__global__ void __launch_bounds__(256) k_final(const int* __restrict__ labels,
                                               float* __restrict__ out) {
    int tid = threadIdx.x, wid = tid >> 5, lane = tid & 31;
    float Dc[NCLS];
    #pragma unroll
    for (int c = 0; c < NCLS; c++) Dc[c] = 0.f;
    for (int i = tid; i < NROWS; i += 256) {
        int l = labels[i];
        float dv = g_d[i];
        #pragma unroll
        for (int c = 0; c < NCLS; c++) Dc[c] += (l == c) ? dv : 0.f;
    }
    __shared__ float red[8][NCLS];
    #pragma unroll
    for (int c = 0; c < NCLS; c++) {
        float w = warpRedSum(Dc[c]);
        if (lane == 0) red[wid][c] = w;
    }
    __syncthreads();
    if (tid == 0) {
        double D[NCLS], Dtot = 0.0;
        for (int c = 0; c < NCLS; c++) {
            double a = 0.0;
            for (int w = 0; w < 8; w++) a += red[w][c];
            D[c] = a;
            Dtot += a;
        }
        double dot_same = 0.0, dot_all = 0.0;
        for (int b = 0; b < NRT; b++) { dot_same += g_dot[b][0]; dot_all += g_dot[b][1]; }

        double num_same = Dtot - dot_same;
        for (int c = 0; c < NCLS; c++) num_same += (double)(g_nc[c] - 1) * D[c];
        double num_total = (double)NROWS * Dtot - dot_all;
        out[0] = (float)(num_same / (num_total - num_same));
    }
}

// ---------------- launch ----------------
extern "C" void kernel_launch(void* const* d_in, const int* in_sizes, int n_in,
                              void* d_out, int out_size) {
    const float* feat   = (const float*)d_in[0];
    const int*   labels = (const int*)d_in[1];
    float*       out    = (float*)d_out;

    k_perm<<<1, 256>>>(labels);
    k_rowstats<<<NROWS, 256>>>(feat);
    k_classsum<<<dim3(NCT, NRT), 256>>>(feat);
    k_dots<<<NRT, 256>>>();
    k_final<<<1, 256>>>(labels, out);
}

// round 2
// speedup vs baseline: 1.0835x; 1.0835x over previous
#include <cuda_runtime.h>
#include <cuda_bf16.h>
#include <math.h>

// Problem constants
#define NROWS 2048
#define NDIM  4096
#define ROWSTRIDE 8192   // features[:,0,:] -> row stride 2*4096 floats
#define NCLS  8

// classsum tiling
#define RT_ROWS 128
#define NRT     16        // 2048 / 128
#define CSTHREADS 128
#define CT_COLS 256       // 128 threads * 2 cols
#define NCT     16        // 4096 / 256

// stage-A reduction
#define NA_BLOCKS 128     // 32768 elements / 256

// ---------------- device scratch (static, no allocation) ----------------
__device__ float    g_off[NROWS];            // m + logZ per row
__device__ float    g_d[NROWS];              // d_i = sum_k p*logp per row
__device__ int      g_perm[NROWS];           // rows sorted by label (stable)
__device__ int      g_slab[NROWS];           // label of g_perm[r]
__device__ int      g_nc[NCLS];              // class counts
__device__ unsigned g_rtmask[NRT];           // classes present in each row tile
__device__ float    g_P[NRT][NCLS][NDIM];    // per-rowtile per-class sum of p
__device__ float    g_L[NRT][NCLS][NDIM];    // per-rowtile per-class sum of logp
__device__ float    g_Ps[NCLS * NDIM];       // class sums over all rows
__device__ float    g_Ls[NCLS * NDIM];
__device__ double   g_psame[NA_BLOCKS];      // partial sum of P_c[k]*L_c[k]
__device__ double   g_pall[16];              // partial sum of Ptot[k]*Ltot[k]

// ---------------- fast exp on the FMA pipe (no MUFU) ----------------
__device__ __forceinline__ float fast_exp(float x) {
    float y = x * 1.4426950408889634f;
    y = fmaxf(y, -126.0f);
    float t = y + 12582912.0f;
    int   ni = __float_as_int(t) - 0x4B400000;
    float n  = t - 12582912.0f;
    float r  = y - n;
    const float c6 = 1.5403530393381609e-4f;
    const float c5 = 1.3333558146428443e-3f;
    const float c4 = 9.618129107628477e-3f;
    const float c3 = 5.550410866482158e-2f;
    const float c2 = 2.402265069591007e-1f;
    const float c1 = 6.931471805599453e-1f;
    float q = c6;
    q = fmaf(q, r, c5);
    q = fmaf(q, r, c4);
    q = fmaf(q, r, c3);
    q = fmaf(q, r, c2);
    q = fmaf(q, r, c1);
    q = fmaf(q, r, 1.0f);
    return q * __int_as_float((ni + 127) << 23);
}

// ---------------- reduction helpers ----------------
__device__ __forceinline__ float warpRedMax(float v) {
    #pragma unroll
    for (int s = 16; s > 0; s >>= 1) v = fmaxf(v, __shfl_xor_sync(0xffffffffu, v, s));
    return v;
}
__device__ __forceinline__ float warpRedSum(float v) {
    #pragma unroll
    for (int s = 16; s > 0; s >>= 1) v += __shfl_xor_sync(0xffffffffu, v, s);
    return v;
}
__device__ __forceinline__ double warpRedSumD(double v) {
    #pragma unroll
    for (int s = 16; s > 0; s >>= 1) v += __shfl_xor_sync(0xffffffffu, v, s);
    return v;
}

// ---------------- kernel 0: stable counting sort of rows by label + tile masks ----------------
__global__ void k_perm(const int* __restrict__ labels) {
    __shared__ int slab[NROWS];
    __shared__ int snc[NCLS];
    __shared__ int scs[NCLS + 1];
    int tid = threadIdx.x;
    for (int i = tid; i < NROWS; i += 256) slab[i] = labels[i];
    __syncthreads();

    int w = tid >> 5, lane = tid & 31;
    if (w < NCLS) {
        int cnt = 0;
        for (int base = 0; base < NROWS; base += 32) {
            int l = slab[base + lane];
            unsigned b = __ballot_sync(0xffffffffu, l == w);
            cnt += __popc(b);
        }
        if (lane == 0) snc[w] = cnt;
    }
    __syncthreads();
    if (tid == 0) {
        int acc = 0;
        for (int c = 0; c < NCLS; c++) { scs[c] = acc; g_nc[c] = snc[c]; acc += snc[c]; }
        scs[NCLS] = acc;
    }
    __syncthreads();
    if (w < NCLS) {
        int off = scs[w];
        for (int base = 0; base < NROWS; base += 32) {
            int l = slab[base + lane];
            unsigned b = __ballot_sync(0xffffffffu, l == w);
            int pre = __popc(b & ((1u << lane) - 1u));
            if (l == w) { g_perm[off + pre] = base + lane; g_slab[off + pre] = w; }
            off += __popc(b);
        }
    }
    __syncthreads();
    // per-rowtile class-present masks (g_slab written by this block, visible after sync)
    if (tid < NRT) {
        unsigned m = 0;
        for (int r = 0; r < RT_ROWS; r++) m |= 1u << g_slab[tid * RT_ROWS + r];
        g_rtmask[tid] = m;
    }
}

// ---------------- kernel 1: per-row softmax stats + diag ----------------
__global__ void __launch_bounds__(256) k_rowstats(const float* __restrict__ feat) {
    int row = blockIdx.x;
    const float4* x4 = (const float4*)(feat + (size_t)row * ROWSTRIDE);
    int tid = threadIdx.x, wid = tid >> 5, lane = tid & 31;

    float4 v[4];
    float m = -INFINITY;
    #pragma unroll
    for (int u = 0; u < 4; u++) {
        v[u] = x4[tid + 256 * u];
        m = fmaxf(m, fmaxf(fmaxf(v[u].x, v[u].y), fmaxf(v[u].z, v[u].w)));
    }

    __shared__ float sred[8];
    __shared__ float sbm;
    float wm = warpRedMax(m);
    if (lane == 0) sred[wid] = wm;
    __syncthreads();
    if (tid == 0) {
        float mm = sred[0];
        #pragma unroll
        for (int i = 1; i < 8; i++) mm = fmaxf(mm, sred[i]);
        sbm = mm;
    }
    __syncthreads();
    m = sbm;

    float s = 0.f, s2 = 0.f;
    #pragma unroll
    for (int u = 0; u < 4; u++) {
        float e0 = fast_exp(v[u].x - m);
        float e1 = fast_exp(v[u].y - m);
        float e2 = fast_exp(v[u].z - m);
        float e3 = fast_exp(v[u].w - m);
        s += e0 + e1 + e2 + e3;
        s2 = fmaf(e0, v[u].x, s2);
        s2 = fmaf(e1, v[u].y, s2);
        s2 = fmaf(e2, v[u].z, s2);
        s2 = fmaf(e3, v[u].w, s2);
    }
    __shared__ float2 sred2[8];
    float ws  = warpRedSum(s);
    float ws2 = warpRedSum(s2);
    if (lane == 0) sred2[wid] = make_float2(ws, ws2);
    __syncthreads();
    if (tid == 0) {
        float Z = 0.f, S2 = 0.f;
        #pragma unroll
        for (int i = 0; i < 8; i++) { Z += sred2[i].x; S2 += sred2[i].y; }
        float o = m + logf(Z);
        g_off[row] = o;
        g_d[row]   = S2 / Z - o;
    }
}

// ---------------- kernel 2: per-class column sums of p and logp ----------------
// grid (NCT, NRT), 128 threads, 2 cols/thread; rows visited class-sorted so a
// single running (P,L) pair suffices; flush only classes present in the tile.
__global__ void __launch_bounds__(CSTHREADS) k_classsum(const float* __restrict__ feat) {
    __shared__ float s_off[RT_ROWS];
    __shared__ int   s_row[RT_ROWS];
    __shared__ int   s_cls[RT_ROWS];
    int tid = threadIdx.x;
    int rt = blockIdx.y, ct = blockIdx.x;
    int rbase = rt * RT_ROWS;
    int k = ct * CT_COLS + tid * 2;

    for (int i = tid; i < RT_ROWS; i += CSTHREADS) {
        int pr = g_perm[rbase + i];
        s_row[i] = pr;
        s_off[i] = g_off[pr];
        s_cls[i] = g_slab[rbase + i];
    }
    __syncthreads();

    float P0 = 0.f, P1 = 0.f, L0 = 0.f, L1 = 0.f;
    int cur = s_cls[0];
    #pragma unroll 4
    for (int r = 0; r < RT_ROWS; r++) {
        int cl = s_cls[r];
        if (cl != cur) {               // warp-uniform, rare
            g_P[rt][cur][k] = P0; g_P[rt][cur][k + 1] = P1;
            g_L[rt][cur][k] = L0; g_L[rt][cur][k + 1] = L1;
            P0 = P1 = L0 = L1 = 0.f;
            cur = cl;
        }
        const float2 xv = *(const float2*)(feat + (size_t)s_row[r] * ROWSTRIDE + k);
        float o = s_off[r];
        float t0 = xv.x - o, t1 = xv.y - o;   // logp
        P0 += fast_exp(t0);
        P1 += fast_exp(t1);
        L0 += t0;
        L1 += t1;
    }
    g_P[rt][cur][k] = P0; g_P[rt][cur][k + 1] = P1;
    g_L[rt][cur][k] = L0; g_L[rt][cur][k + 1] = L1;
}

// ---------------- kernel 3a: reduce over row tiles + same-class dot ----------------
// 128 blocks x 256 threads: thread owns element (c,k); sums only masked tiles.
__global__ void __launch_bounds__(256) k_reduceA() {
    int tid = threadIdx.x, wid = tid >> 5, lane = tid & 31;
    int idx = blockIdx.x * 256 + tid;           // 0..32767
    int c = idx >> 12;
    int k = idx & (NDIM - 1);
    unsigned cbit = 1u << c;

    float P = 0.f, L = 0.f;
    #pragma unroll
    for (int rt = 0; rt < NRT; rt++) {
        if (g_rtmask[rt] & cbit) {
            P += g_P[rt][c][k];
            L += g_L[rt][c][k];
        }
    }
    g_Ps[idx] = P;
    g_Ls[idx] = L;
    double prod = (double)P * (double)L;

    __shared__ double sd[8];
    double w = warpRedSumD(prod);
    if (lane == 0) sd[wid] = w;
    __syncthreads();
    if (tid == 0) {
        double a = 0.0;
        #pragma unroll
        for (int i = 0; i < 8; i++) a += sd[i];
        g_psame[blockIdx.x] = a;
    }
}

// ---------------- kernel 3b: all-pairs dot ----------------
// 16 blocks x 256 threads: thread owns column k; Ptot[k]*Ltot[k].
__global__ void __launch_bounds__(256) k_reduceB() {
    int tid = threadIdx.x, wid = tid >> 5, lane = tid & 31;
    int k = blockIdx.x * 256 + tid;

    float Pt = 0.f, Lt = 0.f;
    #pragma unroll
    for (int c = 0; c < NCLS; c++) {
        Pt += g_Ps[c * NDIM + k];
        Lt += g_Ls[c * NDIM + k];
    }
    double prod = (double)Pt * (double)Lt;

    __shared__ double sd[8];
    double w = warpRedSumD(prod);
    if (lane == 0) sd[wid] = w;
    __syncthreads();
    if (tid == 0) {
        double a = 0.0;
        #pragma unroll
        for (int i = 0; i < 8; i++) a += sd[i];
        g_pall[blockIdx.x] = a;
    }
}

// ---------------- kernel 4: final combine ----------------
__global__ void __launch_bounds__(256) k_final(const int* __restrict__ labels,
                                               float* __restrict__ out) {
    int tid = threadIdx.x, wid = tid >> 5, lane = tid & 31;
    float Dc[NCLS];
    #pragma unroll
    for (int c = 0; c < NCLS; c++) Dc[c] = 0.f;
    for (int i = tid; i < NROWS; i += 256) {
        int l = labels[i];
        float dv = g_d[i];
        #pragma unroll
        for (int c = 0; c < NCLS; c++) Dc[c] += (l == c) ? dv : 0.f;
    }
    __shared__ float red[8][NCLS];
    #pragma unroll
    for (int c = 0; c < NCLS; c++) {
        float w = warpRedSum(Dc[c]);
        if (lane == 0) red[wid][c] = w;
    }
    __syncthreads();
    if (tid == 0) {
        double D[NCLS], Dtot = 0.0;
        for (int c = 0; c < NCLS; c++) {
            double a = 0.0;
            for (int w = 0; w < 8; w++) a += red[w][c];
            D[c] = a;
            Dtot += a;
        }
        double dot_same = 0.0, dot_all = 0.0;
        for (int b = 0; b < NA_BLOCKS; b++) dot_same += g_psame[b];
        for (int b = 0; b < 16; b++)        dot_all  += g_pall[b];

        double num_same = Dtot - dot_same;
        for (int c = 0; c < NCLS; c++) num_same += (double)(g_nc[c] - 1) * D[c];
        double num_total = (double)NROWS * Dtot - dot_all;
        out[0] = (float)(num_same / (num_total - num_same));
    }
}

// ---------------- launch ----------------
extern "C" void kernel_launch(void* const* d_in, const int* in_sizes, int n_in,
                              void* d_out, int out_size) {
    const float* feat   = (const float*)d_in[0];
    const int*   labels = (const int*)d_in[1];
    float*       out    = (float*)d_out;

    k_perm<<<1, 256>>>(labels);
    k_rowstats<<<NROWS, 256>>>(feat);
    k_classsum<<<dim3(NCT, NRT), CSTHREADS>>>(feat);
    k_reduceA<<<NA_BLOCKS, 256>>>();
    k_reduceB<<<16, 256>>>();
    k_final<<<1, 256>>>(labels, out);
}

// round 3
// speedup vs baseline: 1.1590x; 1.0697x over previous
#include <cuda_runtime.h>
#include <cuda_bf16.h>
#include <math.h>

// Problem constants
#define NROWS 2048
#define NDIM  4096
#define ROWSTRIDE 8192   // features[:,0,:] -> row stride 2*4096 floats
#define NCLS  8

// classsum tiling
#define RT_ROWS 128
#define NRT     16        // 2048 / 128
#define CSTHREADS 128
#define CT_COLS 256       // 128 threads * 2 cols
#define NCT     16        // 4096 / 256

// fused reduce
#define NR_BLOCKS 16      // 4096 columns / 256

// ---------------- device scratch (static, no allocation) ----------------
__device__ float    g_off[NROWS];            // m + logZ per row
__device__ float    g_d[NROWS];              // d_i = sum_k p*logp per row
__device__ int      g_perm[NROWS];           // rows sorted by label (stable)
__device__ int      g_slab[NROWS];           // label of g_perm[r]
__device__ int      g_nc[NCLS];              // class counts
__device__ unsigned g_rtmask[NRT];           // classes present in each row tile
__device__ float    g_P[NRT][NCLS][NDIM];    // per-rowtile per-class sum of p
__device__ float    g_L[NRT][NCLS][NDIM];    // per-rowtile per-class sum of logp
__device__ double   g_psame[NR_BLOCKS];      // partial sum of P_c[k]*L_c[k]
__device__ double   g_pall[NR_BLOCKS];       // partial sum of Ptot[k]*Ltot[k]
__device__ unsigned g_ctr;                   // last-block ticket (reset each run)

// ---------------- fast exp on the FMA pipe (no MUFU) ----------------
__device__ __forceinline__ float fast_exp(float x) {
    float y = x * 1.4426950408889634f;
    y = fmaxf(y, -126.0f);
    float t = y + 12582912.0f;
    int   ni = __float_as_int(t) - 0x4B400000;
    float n  = t - 12582912.0f;
    float r  = y - n;
    const float c6 = 1.5403530393381609e-4f;
    const float c5 = 1.3333558146428443e-3f;
    const float c4 = 9.618129107628477e-3f;
    const float c3 = 5.550410866482158e-2f;
    const float c2 = 2.402265069591007e-1f;
    const float c1 = 6.931471805599453e-1f;
    float q = c6;
    q = fmaf(q, r, c5);
    q = fmaf(q, r, c4);
    q = fmaf(q, r, c3);
    q = fmaf(q, r, c2);
    q = fmaf(q, r, c1);
    q = fmaf(q, r, 1.0f);
    return q * __int_as_float((ni + 127) << 23);
}

// ---------------- reduction helpers ----------------
__device__ __forceinline__ float warpRedMax(float v) {
    #pragma unroll
    for (int s = 16; s > 0; s >>= 1) v = fmaxf(v, __shfl_xor_sync(0xffffffffu, v, s));
    return v;
}
__device__ __forceinline__ float warpRedSum(float v) {
    #pragma unroll
    for (int s = 16; s > 0; s >>= 1) v += __shfl_xor_sync(0xffffffffu, v, s);
    return v;
}
__device__ __forceinline__ double warpRedSumD(double v) {
    #pragma unroll
    for (int s = 16; s > 0; s >>= 1) v += __shfl_xor_sync(0xffffffffu, v, s);
    return v;
}

// ---------------- perm block body: stable counting sort by label ----------------
__device__ void perm_body(const int* __restrict__ labels) {
    __shared__ int slab[NROWS];
    __shared__ int snc[NCLS];
    __shared__ int scs[NCLS + 1];
    int tid = threadIdx.x;
    for (int i = tid; i < NROWS; i += 256) slab[i] = labels[i];
    __syncthreads();

    int w = tid >> 5, lane = tid & 31;
    if (w < NCLS) {
        int cnt = 0;
        for (int base = 0; base < NROWS; base += 32) {
            int l = slab[base + lane];
            unsigned b = __ballot_sync(0xffffffffu, l == w);
            cnt += __popc(b);
        }
        if (lane == 0) snc[w] = cnt;
    }
    __syncthreads();
    if (tid == 0) {
        int acc = 0;
        for (int c = 0; c < NCLS; c++) { scs[c] = acc; g_nc[c] = snc[c]; acc += snc[c]; }
        scs[NCLS] = acc;
    }
    __syncthreads();
    if (w < NCLS) {
        int off = scs[w];
        for (int base = 0; base < NROWS; base += 32) {
            int l = slab[base + lane];
            unsigned b = __ballot_sync(0xffffffffu, l == w);
            int pre = __popc(b & ((1u << lane) - 1u));
            if (l == w) { g_perm[off + pre] = base + lane; g_slab[off + pre] = w; }
            off += __popc(b);
        }
    }
    __syncthreads();
    if (tid < NRT) {
        unsigned m = 0;
        for (int r = 0; r < RT_ROWS; r++) m |= 1u << g_slab[tid * RT_ROWS + r];
        g_rtmask[tid] = m;
    }
}

// ---------------- kernel 1: per-row softmax stats (+ perm in last block) ----------------
__global__ void __launch_bounds__(256) k_stats(const float* __restrict__ feat,
                                               const int* __restrict__ labels) {
    if (blockIdx.x == NROWS) { perm_body(labels); return; }

    int row = blockIdx.x;
    const float4* x4 = (const float4*)(feat + (size_t)row * ROWSTRIDE);
    int tid = threadIdx.x, wid = tid >> 5, lane = tid & 31;

    float4 v[4];
    float m = -INFINITY;
    #pragma unroll
    for (int u = 0; u < 4; u++) {
        v[u] = x4[tid + 256 * u];
        m = fmaxf(m, fmaxf(fmaxf(v[u].x, v[u].y), fmaxf(v[u].z, v[u].w)));
    }

    __shared__ float sred[8];
    __shared__ float sbm;
    float wm = warpRedMax(m);
    if (lane == 0) sred[wid] = wm;
    __syncthreads();
    if (tid == 0) {
        float mm = sred[0];
        #pragma unroll
        for (int i = 1; i < 8; i++) mm = fmaxf(mm, sred[i]);
        sbm = mm;
    }
    __syncthreads();
    m = sbm;

    float s = 0.f, s2 = 0.f;
    #pragma unroll
    for (int u = 0; u < 4; u++) {
        float e0 = fast_exp(v[u].x - m);
        float e1 = fast_exp(v[u].y - m);
        float e2 = fast_exp(v[u].z - m);
        float e3 = fast_exp(v[u].w - m);
        s += e0 + e1 + e2 + e3;
        s2 = fmaf(e0, v[u].x, s2);
        s2 = fmaf(e1, v[u].y, s2);
        s2 = fmaf(e2, v[u].z, s2);
        s2 = fmaf(e3, v[u].w, s2);
    }
    __shared__ float2 sred2[8];
    float ws  = warpRedSum(s);
    float ws2 = warpRedSum(s2);
    if (lane == 0) sred2[wid] = make_float2(ws, ws2);
    __syncthreads();
    if (tid == 0) {
        float Z = 0.f, S2 = 0.f;
        #pragma unroll
        for (int i = 0; i < 8; i++) { Z += sred2[i].x; S2 += sred2[i].y; }
        float o = m + logf(Z);
        g_off[row] = o;
        g_d[row]   = S2 / Z - o;
    }
}

// ---------------- kernel 2: per-class column sums of p and logp ----------------
__global__ void __launch_bounds__(CSTHREADS) k_classsum(const float* __restrict__ feat) {
    __shared__ float s_off[RT_ROWS];
    __shared__ int   s_row[RT_ROWS];
    __shared__ int   s_cls[RT_ROWS];
    int tid = threadIdx.x;
    int rt = blockIdx.y, ct = blockIdx.x;
    int rbase = rt * RT_ROWS;
    int k = ct * CT_COLS + tid * 2;

    for (int i = tid; i < RT_ROWS; i += CSTHREADS) {
        int pr = g_perm[rbase + i];
        s_row[i] = pr;
        s_off[i] = g_off[pr];
        s_cls[i] = g_slab[rbase + i];
    }
    __syncthreads();

    float P0 = 0.f, P1 = 0.f, L0 = 0.f, L1 = 0.f;
    int cur = s_cls[0];
    #pragma unroll 4
    for (int r = 0; r < RT_ROWS; r++) {
        int cl = s_cls[r];
        if (cl != cur) {               // warp-uniform, rare
            g_P[rt][cur][k] = P0; g_P[rt][cur][k + 1] = P1;
            g_L[rt][cur][k] = L0; g_L[rt][cur][k + 1] = L1;
            P0 = P1 = L0 = L1 = 0.f;
            cur = cl;
        }
        const float2 xv = *(const float2*)(feat + (size_t)s_row[r] * ROWSTRIDE + k);
        float o = s_off[r];
        float t0 = xv.x - o, t1 = xv.y - o;   // logp
        P0 += fast_exp(t0);
        P1 += fast_exp(t1);
        L0 += t0;
        L1 += t1;
    }
    g_P[rt][cur][k] = P0; g_P[rt][cur][k + 1] = P1;
    g_L[rt][cur][k] = L0; g_L[rt][cur][k + 1] = L1;
}

// ---------------- kernel 3: fused reduce + final (last-block-done) ----------------
// grid NR_BLOCKS x 256; thread owns column k. Per-class sums over masked tiles,
// both dot products in double; last finished block does the scalar combine.
__global__ void __launch_bounds__(256) k_reduce(const int* __restrict__ labels,
                                                float* __restrict__ out) {
    int tid = threadIdx.x, wid = tid >> 5, lane = tid & 31;
    int k = blockIdx.x * 256 + tid;

    __shared__ unsigned smask[NRT];
    if (tid < NRT) smask[tid] = g_rtmask[tid];
    __syncthreads();

    double dsame = 0.0;
    float Pt = 0.f, Lt = 0.f;
    #pragma unroll
    for (int c = 0; c < NCLS; c++) {
        float P = 0.f, L = 0.f;
        unsigned cbit = 1u << c;
        #pragma unroll
        for (int rt = 0; rt < NRT; rt++) {
            if (smask[rt] & cbit) {
                P += g_P[rt][c][k];
                L += g_L[rt][c][k];
            }
        }
        dsame += (double)P * (double)L;
        Pt += P;
        Lt += L;
    }
    double dall = (double)Pt * (double)Lt;

    __shared__ double sd[8][2];
    double w0 = warpRedSumD(dsame);
    double w1 = warpRedSumD(dall);
    if (lane == 0) { sd[wid][0] = w0; sd[wid][1] = w1; }
    __syncthreads();
    __shared__ bool is_last;
    if (tid == 0) {
        double a = 0.0, b = 0.0;
        #pragma unroll
        for (int i = 0; i < 8; i++) { a += sd[i][0]; b += sd[i][1]; }
        g_psame[blockIdx.x] = a;
        g_pall[blockIdx.x]  = b;
        __threadfence();
        unsigned t = atomicAdd(&g_ctr, 1u);
        is_last = (t == NR_BLOCKS - 1);
    }
    __syncthreads();
    if (!is_last) return;

    // ---- final combine (one block) ----
    __threadfence();
    float Dc[NCLS];
    #pragma unroll
    for (int c = 0; c < NCLS; c++) Dc[c] = 0.f;
    for (int i = tid; i < NROWS; i += 256) {
        int l = labels[i];
        float dv = g_d[i];
        #pragma unroll
        for (int c = 0; c < NCLS; c++) Dc[c] += (l == c) ? dv : 0.f;
    }
    __shared__ float red[8][NCLS];
    #pragma unroll
    for (int c = 0; c < NCLS; c++) {
        float w = warpRedSum(Dc[c]);
        if (lane == 0) red[wid][c] = w;
    }
    __syncthreads();
    if (tid == 0) {
        double D[NCLS], Dtot = 0.0;
        for (int c = 0; c < NCLS; c++) {
            double a = 0.0;
            for (int w = 0; w < 8; w++) a += red[w][c];
            D[c] = a;
            Dtot += a;
        }
        double dot_same = 0.0, dot_all = 0.0;
        for (int b = 0; b < NR_BLOCKS; b++) { dot_same += g_psame[b]; dot_all += g_pall[b]; }

        double num_same = Dtot - dot_same;
        for (int c = 0; c < NCLS; c++) num_same += (double)(g_nc[c] - 1) * D[c];
        double num_total = (double)NROWS * Dtot - dot_all;
        out[0] = (float)(num_same / (num_total - num_same));
        g_ctr = 0;                      // reset for next graph replay
    }
}

// ---------------- launch ----------------
extern "C" void kernel_launch(void* const* d_in, const int* in_sizes, int n_in,
                              void* d_out, int out_size) {
    const float* feat   = (const float*)d_in[0];
    const int*   labels = (const int*)d_in[1];
    float*       out    = (float*)d_out;

    k_stats<<<NROWS + 1, 256>>>(feat, labels);
    k_classsum<<<dim3(NCT, NRT), CSTHREADS>>>(feat);
    k_reduce<<<NR_BLOCKS, 256>>>(labels, out);
}